// round 12
// baseline (speedup 1.0000x reference)
#include <cuda_runtime.h>
#include <cuda_fp16.h>
#include <stdint.h>
#include <math.h>

#define NROWS (8 * 2048)
#define EDIM  512
#define HEADS 8
#define HDIM  64
#define SEQ   2048
#define BATCH 8
#define LOG2E 1.44269504f

// fp16 scratch (device globals: allocation-free per harness rules)
__device__ __align__(16) __half g_qh[NROWS * EDIM];
__device__ __align__(16) __half g_kh[NROWS * EDIM];
__device__ __align__(16) __half g_vh[NROWS * EDIM];
__device__ __align__(16) __half g_aoh[NROWS * EDIM];
__device__ __align__(16) __half g_wt[4 * EDIM * EDIM]; // 4 weights, [n][k] fp16

// ---------------------------------------------------------------------------
// PTX helpers
// ---------------------------------------------------------------------------
__device__ __forceinline__ uint32_t sptr(const void* p) {
    return (uint32_t)__cvta_generic_to_shared(p);
}

__device__ __forceinline__ void mma16816(float* c, const uint32_t* a,
                                         uint32_t b0, uint32_t b1)
{
    asm volatile(
        "mma.sync.aligned.m16n8k16.row.col.f32.f16.f16.f32 "
        "{%0,%1,%2,%3}, {%4,%5,%6,%7}, {%8,%9}, {%0,%1,%2,%3};"
        : "+f"(c[0]), "+f"(c[1]), "+f"(c[2]), "+f"(c[3])
        : "r"(a[0]), "r"(a[1]), "r"(a[2]), "r"(a[3]), "r"(b0), "r"(b1));
}

__device__ __forceinline__ void ldsm4(uint32_t& r0, uint32_t& r1,
                                      uint32_t& r2, uint32_t& r3, uint32_t a)
{
    asm volatile("ldmatrix.sync.aligned.m8n8.x4.shared.b16 {%0,%1,%2,%3}, [%4];"
                 : "=r"(r0), "=r"(r1), "=r"(r2), "=r"(r3) : "r"(a));
}

__device__ __forceinline__ void ldsm4t(uint32_t& r0, uint32_t& r1,
                                       uint32_t& r2, uint32_t& r3, uint32_t a)
{
    asm volatile("ldmatrix.sync.aligned.m8n8.x4.trans.shared.b16 {%0,%1,%2,%3}, [%4];"
                 : "=r"(r0), "=r"(r1), "=r"(r2), "=r"(r3) : "r"(a));
}

// ---------------------------------------------------------------------------
// Weight transpose+convert: Wt[n][k] = W[k][n], fp32 -> fp16.
// ---------------------------------------------------------------------------
__global__ void wt_convert_kernel(const float* __restrict__ W,
                                  __half* __restrict__ Wt)
{
    __shared__ float tile[32][33];
    int x = blockIdx.x * 32 + threadIdx.x;
    int y = blockIdx.y * 32 + threadIdx.y;
    #pragma unroll
    for (int i = 0; i < 32; i += 8)
        tile[threadIdx.y + i][threadIdx.x] = W[(size_t)(y + i) * EDIM + x];
    __syncthreads();
    int nk = blockIdx.y * 32 + threadIdx.x;
    int nn = blockIdx.x * 32 + threadIdx.y;
    #pragma unroll
    for (int i = 0; i < 32; i += 8)
        Wt[(size_t)(nn + i) * EDIM + nk] =
            __float2half(tile[threadIdx.x][threadIdx.y + i]);
}

// ---------------------------------------------------------------------------
// HGEMM: C[16384,512] = A @ Wt^T + bias. Block 128x128, k-step 32, 8 warps.
// blockIdx.z selects {A, bias, out, weight-slice} (QKV batched in one launch).
// A is fp32 (converted during staging) when AF32, else fp16.
// Double-buffered smem + register-prefetched GMEM loads + ldmatrix fragments.
// (verbatim from round 10 — hardware-verified)
// ---------------------------------------------------------------------------
template <bool AF32, bool HALF_OUT>
__global__ void __launch_bounds__(256, 2) hgemm_bias(
    const void* __restrict__ A0, const void* __restrict__ A1,
    const void* __restrict__ A2, const __half* __restrict__ WtBase,
    const float* __restrict__ bias0, const float* __restrict__ bias1,
    const float* __restrict__ bias2,
    void* __restrict__ O0, void* __restrict__ O1, void* __restrict__ O2)
{
    __shared__ __align__(16) __half As[2][128][40];
    __shared__ __align__(16) __half Bs[2][128][40];

    const int z = blockIdx.z;
    const void*  A    = (z == 0) ? A0 : (z == 1) ? A1 : A2;
    const float* bias = (z == 0) ? bias0 : (z == 1) ? bias1 : bias2;
    void*        Cout = (z == 0) ? O0 : (z == 1) ? O1 : O2;
    const __half* Wt  = WtBase + (size_t)z * EDIM * EDIM;

    const int tid  = threadIdx.x;
    const int lane = tid & 31, warp = tid >> 5;
    const int gid  = lane >> 2, tig = lane & 3;
    const int g8   = lane >> 3, i8 = lane & 7;
    const int wm = warp >> 1, wn = warp & 1;
    const int rowBlock = blockIdx.y * 128, colBlock = blockIdx.x * 128;
    const int m0 = wm * 32, n0 = wn * 64;

    float c[2][8][4];
    #pragma unroll
    for (int mt = 0; mt < 2; mt++)
        #pragma unroll
        for (int nt = 0; nt < 8; nt++)
            #pragma unroll
            for (int i = 0; i < 4; i++) c[mt][nt][i] = 0.f;

    float4 aF[4];
    uint4  aH[2];
    uint4  bR[2];

#define LDG_TILE(kt) do {                                                     \
    int k0_ = (kt) * 32;                                                      \
    if (AF32) {                                                               \
        const float* Af_ = (const float*)A;                                   \
        for (int j = 0; j < 4; j++) {                                         \
            int task = tid + j * 256, r = task >> 3, cc = (task & 7) * 4;     \
            aF[j] = *(const float4*)(Af_ + (size_t)(rowBlock + r) * EDIM + k0_ + cc); \
        }                                                                     \
    } else {                                                                  \
        const __half* Ah_ = (const __half*)A;                                 \
        for (int j = 0; j < 2; j++) {                                         \
            int task = tid + j * 256, r = task >> 2, cc = (task & 3) * 8;     \
            aH[j] = *(const uint4*)(Ah_ + (size_t)(rowBlock + r) * EDIM + k0_ + cc); \
        }                                                                     \
    }                                                                         \
    for (int j = 0; j < 2; j++) {                                             \
        int task = tid + j * 256, r = task >> 2, cc = (task & 3) * 8;         \
        bR[j] = *(const uint4*)(Wt + (size_t)(colBlock + r) * EDIM + k0_ + cc); \
    }                                                                         \
} while (0)

#define STS_TILE(bf_) do {                                                    \
    if (AF32) {                                                               \
        for (int j = 0; j < 4; j++) {                                         \
            int task = tid + j * 256, r = task >> 3, cc = (task & 7) * 4;     \
            __half2 h0_ = __floats2half2_rn(aF[j].x, aF[j].y);                \
            __half2 h1_ = __floats2half2_rn(aF[j].z, aF[j].w);                \
            uint2 u_; u_.x = *(uint32_t*)&h0_; u_.y = *(uint32_t*)&h1_;       \
            *(uint2*)&As[bf_][r][cc] = u_;                                    \
        }                                                                     \
    } else {                                                                  \
        for (int j = 0; j < 2; j++) {                                         \
            int task = tid + j * 256, r = task >> 2, cc = (task & 3) * 8;     \
            *(uint4*)&As[bf_][r][cc] = aH[j];                                 \
        }                                                                     \
    }                                                                         \
    for (int j = 0; j < 2; j++) {                                             \
        int task = tid + j * 256, r = task >> 2, cc = (task & 3) * 8;         \
        *(uint4*)&Bs[bf_][r][cc] = bR[j];                                     \
    }                                                                         \
} while (0)

    LDG_TILE(0);
    STS_TILE(0);
    __syncthreads();

    for (int it = 0; it < 16; it++) {
        const int buf = it & 1;
        if (it < 15) LDG_TILE(it + 1);

        #pragma unroll
        for (int t = 0; t < 2; t++) {
            const int kk = t * 16;
            uint32_t af[2][4], bf[4][4];
            #pragma unroll
            for (int mt = 0; mt < 2; mt++)
                ldsm4(af[mt][0], af[mt][1], af[mt][2], af[mt][3],
                      sptr(&As[buf][m0 + mt * 16 + i8 + 8 * (g8 & 1)]
                              [kk + 8 * (g8 >> 1)]));
            #pragma unroll
            for (int np = 0; np < 4; np++)
                ldsm4(bf[np][0], bf[np][1], bf[np][2], bf[np][3],
                      sptr(&Bs[buf][n0 + np * 16 + i8 + 8 * (g8 >> 1)]
                              [kk + 8 * (g8 & 1)]));
            #pragma unroll
            for (int mt = 0; mt < 2; mt++)
                #pragma unroll
                for (int np = 0; np < 4; np++) {
                    mma16816(c[mt][2 * np],     af[mt], bf[np][0], bf[np][1]);
                    mma16816(c[mt][2 * np + 1], af[mt], bf[np][2], bf[np][3]);
                }
        }

        if (it < 15) STS_TILE(buf ^ 1);
        __syncthreads();
    }

    #pragma unroll
    for (int mt = 0; mt < 2; mt++) {
        int r0 = rowBlock + m0 + mt * 16 + gid;
        #pragma unroll
        for (int nt = 0; nt < 8; nt++) {
            int col = colBlock + n0 + nt * 8 + tig * 2;
            float b0v = bias[col], b1v = bias[col + 1];
            if (HALF_OUT) {
                __half* o = (__half*)Cout;
                *reinterpret_cast<__half2*>(o + (size_t)r0 * EDIM + col) =
                    __floats2half2_rn(c[mt][nt][0] + b0v, c[mt][nt][1] + b1v);
                *reinterpret_cast<__half2*>(o + (size_t)(r0 + 8) * EDIM + col) =
                    __floats2half2_rn(c[mt][nt][2] + b0v, c[mt][nt][3] + b1v);
            } else {
                float* o = (float*)Cout;
                *reinterpret_cast<float2*>(o + (size_t)r0 * EDIM + col) =
                    make_float2(c[mt][nt][0] + b0v, c[mt][nt][1] + b1v);
                *reinterpret_cast<float2*>(o + (size_t)(r0 + 8) * EDIM + col) =
                    make_float2(c[mt][nt][2] + b0v, c[mt][nt][3] + b1v);
            }
        }
    }
#undef LDG_TILE
#undef STS_TILE
}

// ---------------------------------------------------------------------------
// Flash attention, HMMA. Br=128, Bc=64, 8 warps; warp w owns rows w*16..+15.
// THIS ROUND: ldmatrix fragment loads (Q/K ldsm4, V natural layout + ldsm4t,
// no transpose staging). Loads remain synchronous; smem static; mask as
// in round 8. Softmax stats register-resident.
// ---------------------------------------------------------------------------
__global__ void __launch_bounds__(256) flash_hmma(const int* __restrict__ mask)
{
    __shared__ __align__(16) __half sQ[128][72];
    __shared__ __align__(16) __half sK[64][72];
    __shared__ __align__(16) __half sV[64][72];    // natural [key][d]
    __shared__ float sMaskF[64];

    const int tid  = threadIdx.x;
    const int lane = tid & 31, warp = tid >> 5;
    const int gid  = lane >> 2, tig = lane & 3;
    const int g8   = lane >> 3, i8 = lane & 7;
    const int qt = blockIdx.x, h = blockIdx.y, b = blockIdx.z;
    const int qRow0 = b * SEQ + qt * 128;
    const int colBase = h * HDIM;
    const int wr0 = warp * 16;

    // Q tile: 128 x 64 halfs = 1024 uint4
    #pragma unroll
    for (int i = 0; i < 4; i++) {
        int idx = tid + i * 256;
        int r = idx >> 3, seg = idx & 7;
        *reinterpret_cast<uint4*>(&sQ[r][seg * 8]) =
            *reinterpret_cast<const uint4*>(
                g_qh + (size_t)(qRow0 + r) * EDIM + colBase + seg * 8);
    }
    __syncthreads();

    uint32_t qf[4][4];
    #pragma unroll
    for (int t = 0; t < 4; t++)
        ldsm4(qf[t][0], qf[t][1], qf[t][2], qf[t][3],
              sptr(&sQ[wr0 + i8 + 8 * (g8 & 1)][t * 16 + 8 * (g8 >> 1)]));

    float of[8][4];
    #pragma unroll
    for (int nt = 0; nt < 8; nt++)
        #pragma unroll
        for (int i = 0; i < 4; i++) of[nt][i] = 0.f;
    float m_lo = -1e30f, m_hi = -1e30f, l_lo = 0.f, l_hi = 0.f;

    for (int kc = 0; kc < SEQ / 64; kc++) {
        const int kRow0 = b * SEQ + kc * 64;

        // K and V tiles: 64 x 64 halfs = 512 uint4 each, natural layout
        #pragma unroll
        for (int i = 0; i < 2; i++) {
            int idx = tid + i * 256;
            int r = idx >> 3, seg = idx & 7;
            size_t off = (size_t)(kRow0 + r) * EDIM + colBase + seg * 8;
            *reinterpret_cast<uint4*>(&sK[r][seg * 8]) =
                *reinterpret_cast<const uint4*>(g_kh + off);
            *reinterpret_cast<uint4*>(&sV[r][seg * 8]) =
                *reinterpret_cast<const uint4*>(g_vh + off);
        }
        if (tid < 64) {
            int mi = mask[b * SEQ + kc * 64 + tid];
            sMaskF[tid] = mi ? (-1.0e9f * LOG2E) : 0.f;
        }
        __syncthreads();

        // S = Q K^T (fp32 frags), K B-fragments via ldsm4
        float sf[8][4];
        #pragma unroll
        for (int nt = 0; nt < 8; nt++)
            #pragma unroll
            for (int i = 0; i < 4; i++) sf[nt][i] = 0.f;
        #pragma unroll
        for (int t = 0; t < 4; t++)
            #pragma unroll
            for (int np = 0; np < 4; np++) {
                uint32_t k0r, k1r, k2r, k3r;
                ldsm4(k0r, k1r, k2r, k3r,
                      sptr(&sK[np * 16 + i8 + 8 * (g8 >> 1)]
                              [t * 16 + 8 * (g8 & 1)]));
                mma16816(sf[2 * np],     qf[t], k0r, k1r);
                mma16816(sf[2 * np + 1], qf[t], k2r, k3r);
            }

        // scale into log2 domain + mask, then online softmax
        const float sc = 0.125f * LOG2E;
        float mx_lo = -1e30f, mx_hi = -1e30f;
        #pragma unroll
        for (int nt = 0; nt < 8; nt++) {
            float p0 = sMaskF[nt * 8 + tig * 2];
            float p1 = sMaskF[nt * 8 + tig * 2 + 1];
            sf[nt][0] = fmaf(sf[nt][0], sc, p0);
            sf[nt][1] = fmaf(sf[nt][1], sc, p1);
            sf[nt][2] = fmaf(sf[nt][2], sc, p0);
            sf[nt][3] = fmaf(sf[nt][3], sc, p1);
            mx_lo = fmaxf(mx_lo, fmaxf(sf[nt][0], sf[nt][1]));
            mx_hi = fmaxf(mx_hi, fmaxf(sf[nt][2], sf[nt][3]));
        }
        mx_lo = fmaxf(mx_lo, __shfl_xor_sync(0xffffffffu, mx_lo, 1));
        mx_lo = fmaxf(mx_lo, __shfl_xor_sync(0xffffffffu, mx_lo, 2));
        mx_hi = fmaxf(mx_hi, __shfl_xor_sync(0xffffffffu, mx_hi, 1));
        mx_hi = fmaxf(mx_hi, __shfl_xor_sync(0xffffffffu, mx_hi, 2));
        float mn_lo = fmaxf(m_lo, mx_lo), mn_hi = fmaxf(m_hi, mx_hi);
        float al_lo = exp2f(m_lo - mn_lo), al_hi = exp2f(m_hi - mn_hi);

        float sum_lo = 0.f, sum_hi = 0.f;
        uint32_t pf[4][4];
        #pragma unroll
        for (int nt = 0; nt < 8; nt++) {
            float p0 = exp2f(sf[nt][0] - mn_lo);
            float p1 = exp2f(sf[nt][1] - mn_lo);
            float p2 = exp2f(sf[nt][2] - mn_hi);
            float p3 = exp2f(sf[nt][3] - mn_hi);
            sum_lo += p0 + p1; sum_hi += p2 + p3;
            int t = nt >> 1;
            __half2 lo2 = __floats2half2_rn(p0, p1);
            __half2 hi2 = __floats2half2_rn(p2, p3);
            if ((nt & 1) == 0) {
                pf[t][0] = *reinterpret_cast<uint32_t*>(&lo2);
                pf[t][1] = *reinterpret_cast<uint32_t*>(&hi2);
            } else {
                pf[t][2] = *reinterpret_cast<uint32_t*>(&lo2);
                pf[t][3] = *reinterpret_cast<uint32_t*>(&hi2);
            }
        }
        sum_lo += __shfl_xor_sync(0xffffffffu, sum_lo, 1);
        sum_lo += __shfl_xor_sync(0xffffffffu, sum_lo, 2);
        sum_hi += __shfl_xor_sync(0xffffffffu, sum_hi, 1);
        sum_hi += __shfl_xor_sync(0xffffffffu, sum_hi, 2);
        l_lo = l_lo * al_lo + sum_lo;  m_lo = mn_lo;
        l_hi = l_hi * al_hi + sum_hi;  m_hi = mn_hi;

        #pragma unroll
        for (int nt = 0; nt < 8; nt++) {
            of[nt][0] *= al_lo; of[nt][1] *= al_lo;
            of[nt][2] *= al_hi; of[nt][3] *= al_hi;
        }

        // O += P @ V   (V natural [key][d], B-fragments via ldsm4t)
        #pragma unroll
        for (int t = 0; t < 4; t++)
            #pragma unroll
            for (int np = 0; np < 4; np++) {
                uint32_t v0r, v1r, v2r, v3r;
                ldsm4t(v0r, v1r, v2r, v3r,
                       sptr(&sV[t * 16 + i8 + 8 * (g8 & 1)]
                               [(2 * np + (g8 >> 1)) * 8]));
                mma16816(of[2 * np],     pf[t], v0r, v1r);
                mma16816(of[2 * np + 1], pf[t], v2r, v3r);
            }
        __syncthreads();
    }

    float r_lo = 1.f / l_lo, r_hi = 1.f / l_hi;
    #pragma unroll
    for (int nt = 0; nt < 8; nt++) {
        int col = colBase + nt * 8 + tig * 2;
        *reinterpret_cast<__half2*>(
            g_aoh + (size_t)(qRow0 + wr0 + gid) * EDIM + col) =
            __floats2half2_rn(of[nt][0] * r_lo, of[nt][1] * r_lo);
        *reinterpret_cast<__half2*>(
            g_aoh + (size_t)(qRow0 + wr0 + gid + 8) * EDIM + col) =
            __floats2half2_rn(of[nt][2] * r_hi, of[nt][3] * r_hi);
    }
}

// ---------------------------------------------------------------------------
extern "C" void kernel_launch(void* const* d_in, const int* in_sizes, int n_in,
                              void* d_out, int out_size)
{
    (void)in_sizes; (void)n_in; (void)out_size;
    const float* value = (const float*)d_in[0];
    const float* key_  = (const float*)d_in[1];
    const float* query = (const float*)d_in[2];
    const int*   mask  = (const int*)d_in[3];
    const float* wq = (const float*)d_in[4];
    const float* bq = (const float*)d_in[5];
    const float* wk = (const float*)d_in[6];
    const float* bk = (const float*)d_in[7];
    const float* wv = (const float*)d_in[8];
    const float* bv = (const float*)d_in[9];
    const float* wo = (const float*)d_in[10];
    const float* bo = (const float*)d_in[11];
    float* out = (float*)d_out;

    __half *qh, *kh, *vh, *aoh, *wt;
    cudaGetSymbolAddress((void**)&qh,  g_qh);
    cudaGetSymbolAddress((void**)&kh,  g_kh);
    cudaGetSymbolAddress((void**)&vh,  g_vh);
    cudaGetSymbolAddress((void**)&aoh, g_aoh);
    cudaGetSymbolAddress((void**)&wt,  g_wt);
    __half* wt3 = wt + 3 * (size_t)EDIM * EDIM;

    dim3 tGrid(16, 16), tBlk(32, 8);
    wt_convert_kernel<<<tGrid, tBlk>>>(wq, wt);
    wt_convert_kernel<<<tGrid, tBlk>>>(wk, wt + (size_t)EDIM * EDIM);
    wt_convert_kernel<<<tGrid, tBlk>>>(wv, wt + 2 * (size_t)EDIM * EDIM);
    wt_convert_kernel<<<tGrid, tBlk>>>(wo, wt3);

    // Q, K, V projections batched in one launch (fp32 in, fp16 out)
    hgemm_bias<true, true><<<dim3(EDIM / 128, NROWS / 128, 3), 256>>>(
        query, key_, value, wt, bq, bk, bv, qh, kh, vh);

    flash_hmma<<<dim3(SEQ / 128, HEADS, BATCH), 256>>>(mask);

    // Output projection (fp16 in, fp32 out)
    hgemm_bias<false, false><<<dim3(EDIM / 128, NROWS / 128, 1), 256>>>(
        aoh, aoh, aoh, wt3, bo, bo, bo, out, out, out);
}

// round 15
// speedup vs baseline: 1.3118x; 1.3118x over previous
#include <cuda_runtime.h>
#include <cuda_fp16.h>
#include <stdint.h>
#include <math.h>

#define NROWS (8 * 2048)
#define EDIM  512
#define HEADS 8
#define HDIM  64
#define SEQ   2048
#define BATCH 8
#define LOG2E 1.44269504f

// fp16 scratch (device globals: allocation-free per harness rules)
__device__ __align__(16) __half g_qh[NROWS * EDIM];
__device__ __align__(16) __half g_kh[NROWS * EDIM];
__device__ __align__(16) __half g_vh[NROWS * EDIM];
__device__ __align__(16) __half g_aoh[NROWS * EDIM];
__device__ __align__(16) __half g_wt[4 * EDIM * EDIM]; // 4 weights, [n][k] fp16

// ---------------------------------------------------------------------------
// PTX helpers
// ---------------------------------------------------------------------------
__device__ __forceinline__ uint32_t sptr(const void* p) {
    return (uint32_t)__cvta_generic_to_shared(p);
}

__device__ __forceinline__ void mma16816(float* c, const uint32_t* a,
                                         uint32_t b0, uint32_t b1)
{
    asm volatile(
        "mma.sync.aligned.m16n8k16.row.col.f32.f16.f16.f32 "
        "{%0,%1,%2,%3}, {%4,%5,%6,%7}, {%8,%9}, {%0,%1,%2,%3};"
        : "+f"(c[0]), "+f"(c[1]), "+f"(c[2]), "+f"(c[3])
        : "r"(a[0]), "r"(a[1]), "r"(a[2]), "r"(a[3]), "r"(b0), "r"(b1));
}

__device__ __forceinline__ void ldsm4(uint32_t& r0, uint32_t& r1,
                                      uint32_t& r2, uint32_t& r3, uint32_t a)
{
    asm volatile("ldmatrix.sync.aligned.m8n8.x4.shared.b16 {%0,%1,%2,%3}, [%4];"
                 : "=r"(r0), "=r"(r1), "=r"(r2), "=r"(r3) : "r"(a));
}

__device__ __forceinline__ void ldsm4t(uint32_t& r0, uint32_t& r1,
                                       uint32_t& r2, uint32_t& r3, uint32_t a)
{
    asm volatile("ldmatrix.sync.aligned.m8n8.x4.trans.shared.b16 {%0,%1,%2,%3}, [%4];"
                 : "=r"(r0), "=r"(r1), "=r"(r2), "=r"(r3) : "r"(a));
}

#define CP16(d, s) \
    asm volatile("cp.async.cg.shared.global [%0], [%1], 16;" :: "r"(d), "l"(s))
#define CP_COMMIT() asm volatile("cp.async.commit_group;" ::: "memory")

// ---------------------------------------------------------------------------
// Weight transpose+convert: Wt[n][k] = W[k][n], fp32 -> fp16.
// ---------------------------------------------------------------------------
__global__ void wt_convert_kernel(const float* __restrict__ W,
                                  __half* __restrict__ Wt)
{
    __shared__ float tile[32][33];
    int x = blockIdx.x * 32 + threadIdx.x;
    int y = blockIdx.y * 32 + threadIdx.y;
    #pragma unroll
    for (int i = 0; i < 32; i += 8)
        tile[threadIdx.y + i][threadIdx.x] = W[(size_t)(y + i) * EDIM + x];
    __syncthreads();
    int nk = blockIdx.y * 32 + threadIdx.x;
    int nn = blockIdx.x * 32 + threadIdx.y;
    #pragma unroll
    for (int i = 0; i < 32; i += 8)
        Wt[(size_t)(nn + i) * EDIM + nk] =
            __float2half(tile[threadIdx.x][threadIdx.y + i]);
}

// ---------------------------------------------------------------------------
// HGEMM (verbatim, hardware-verified): C = A @ Wt^T + bias.
// Block 128x128, k-step 32, 8 warps; QKV batched via blockIdx.z.
// ---------------------------------------------------------------------------
template <bool AF32, bool HALF_OUT>
__global__ void __launch_bounds__(256, 2) hgemm_bias(
    const void* __restrict__ A0, const void* __restrict__ A1,
    const void* __restrict__ A2, const __half* __restrict__ WtBase,
    const float* __restrict__ bias0, const float* __restrict__ bias1,
    const float* __restrict__ bias2,
    void* __restrict__ O0, void* __restrict__ O1, void* __restrict__ O2)
{
    __shared__ __align__(16) __half As[2][128][40];
    __shared__ __align__(16) __half Bs[2][128][40];

    const int z = blockIdx.z;
    const void*  A    = (z == 0) ? A0 : (z == 1) ? A1 : A2;
    const float* bias = (z == 0) ? bias0 : (z == 1) ? bias1 : bias2;
    void*        Cout = (z == 0) ? O0 : (z == 1) ? O1 : O2;
    const __half* Wt  = WtBase + (size_t)z * EDIM * EDIM;

    const int tid  = threadIdx.x;
    const int lane = tid & 31, warp = tid >> 5;
    const int gid  = lane >> 2, tig = lane & 3;
    const int g8   = lane >> 3, i8 = lane & 7;
    const int wm = warp >> 1, wn = warp & 1;
    const int rowBlock = blockIdx.y * 128, colBlock = blockIdx.x * 128;
    const int m0 = wm * 32, n0 = wn * 64;

    float c[2][8][4];
    #pragma unroll
    for (int mt = 0; mt < 2; mt++)
        #pragma unroll
        for (int nt = 0; nt < 8; nt++)
            #pragma unroll
            for (int i = 0; i < 4; i++) c[mt][nt][i] = 0.f;

    float4 aF[4];
    uint4  aH[2];
    uint4  bR[2];

#define LDG_TILE(kt) do {                                                     \
    int k0_ = (kt) * 32;                                                      \
    if (AF32) {                                                               \
        const float* Af_ = (const float*)A;                                   \
        for (int j = 0; j < 4; j++) {                                         \
            int task = tid + j * 256, r = task >> 3, cc = (task & 7) * 4;     \
            aF[j] = *(const float4*)(Af_ + (size_t)(rowBlock + r) * EDIM + k0_ + cc); \
        }                                                                     \
    } else {                                                                  \
        const __half* Ah_ = (const __half*)A;                                 \
        for (int j = 0; j < 2; j++) {                                         \
            int task = tid + j * 256, r = task >> 2, cc = (task & 3) * 8;     \
            aH[j] = *(const uint4*)(Ah_ + (size_t)(rowBlock + r) * EDIM + k0_ + cc); \
        }                                                                     \
    }                                                                         \
    for (int j = 0; j < 2; j++) {                                             \
        int task = tid + j * 256, r = task >> 2, cc = (task & 3) * 8;         \
        bR[j] = *(const uint4*)(Wt + (size_t)(colBlock + r) * EDIM + k0_ + cc); \
    }                                                                         \
} while (0)

#define STS_TILE(bf_) do {                                                    \
    if (AF32) {                                                               \
        for (int j = 0; j < 4; j++) {                                         \
            int task = tid + j * 256, r = task >> 3, cc = (task & 7) * 4;     \
            __half2 h0_ = __floats2half2_rn(aF[j].x, aF[j].y);                \
            __half2 h1_ = __floats2half2_rn(aF[j].z, aF[j].w);                \
            uint2 u_; u_.x = *(uint32_t*)&h0_; u_.y = *(uint32_t*)&h1_;       \
            *(uint2*)&As[bf_][r][cc] = u_;                                    \
        }                                                                     \
    } else {                                                                  \
        for (int j = 0; j < 2; j++) {                                         \
            int task = tid + j * 256, r = task >> 2, cc = (task & 3) * 8;     \
            *(uint4*)&As[bf_][r][cc] = aH[j];                                 \
        }                                                                     \
    }                                                                         \
    for (int j = 0; j < 2; j++) {                                             \
        int task = tid + j * 256, r = task >> 2, cc = (task & 3) * 8;         \
        *(uint4*)&Bs[bf_][r][cc] = bR[j];                                     \
    }                                                                         \
} while (0)

    LDG_TILE(0);
    STS_TILE(0);
    __syncthreads();

    for (int it = 0; it < 16; it++) {
        const int buf = it & 1;
        if (it < 15) LDG_TILE(it + 1);

        #pragma unroll
        for (int t = 0; t < 2; t++) {
            const int kk = t * 16;
            uint32_t af[2][4], bf[4][4];
            #pragma unroll
            for (int mt = 0; mt < 2; mt++)
                ldsm4(af[mt][0], af[mt][1], af[mt][2], af[mt][3],
                      sptr(&As[buf][m0 + mt * 16 + i8 + 8 * (g8 & 1)]
                              [kk + 8 * (g8 >> 1)]));
            #pragma unroll
            for (int np = 0; np < 4; np++)
                ldsm4(bf[np][0], bf[np][1], bf[np][2], bf[np][3],
                      sptr(&Bs[buf][n0 + np * 16 + i8 + 8 * (g8 >> 1)]
                              [kk + 8 * (g8 & 1)]));
            #pragma unroll
            for (int mt = 0; mt < 2; mt++)
                #pragma unroll
                for (int np = 0; np < 4; np++) {
                    mma16816(c[mt][2 * np],     af[mt], bf[np][0], bf[np][1]);
                    mma16816(c[mt][2 * np + 1], af[mt], bf[np][2], bf[np][3]);
                }
        }

        if (it < 15) STS_TILE(buf ^ 1);
        __syncthreads();
    }

    #pragma unroll
    for (int mt = 0; mt < 2; mt++) {
        int r0 = rowBlock + m0 + mt * 16 + gid;
        #pragma unroll
        for (int nt = 0; nt < 8; nt++) {
            int col = colBlock + n0 + nt * 8 + tig * 2;
            float b0v = bias[col], b1v = bias[col + 1];
            if (HALF_OUT) {
                __half* o = (__half*)Cout;
                *reinterpret_cast<__half2*>(o + (size_t)r0 * EDIM + col) =
                    __floats2half2_rn(c[mt][nt][0] + b0v, c[mt][nt][1] + b1v);
                *reinterpret_cast<__half2*>(o + (size_t)(r0 + 8) * EDIM + col) =
                    __floats2half2_rn(c[mt][nt][2] + b0v, c[mt][nt][3] + b1v);
            } else {
                float* o = (float*)Cout;
                *reinterpret_cast<float2*>(o + (size_t)r0 * EDIM + col) =
                    make_float2(c[mt][nt][0] + b0v, c[mt][nt][1] + b1v);
                *reinterpret_cast<float2*>(o + (size_t)(r0 + 8) * EDIM + col) =
                    make_float2(c[mt][nt][2] + b0v, c[mt][nt][3] + b1v);
            }
        }
    }
#undef LDG_TILE
#undef STS_TILE
}

// ---------------------------------------------------------------------------
// Flash attention, HMMA. Br=128, Bc=64, 8 warps; warp w owns rows w*16..+15.
// cp.async double-buffered K/V (32 kc iterations -> guard is kc<31, the
// round-9/13 bug was kc<15); mask converted once per CTA in the preamble.
// Fragment paths hardware-verified in round 12.
// ---------------------------------------------------------------------------
// smem: sQ 18432 | sK 2x9216 | sV 2x9216 | maskrow 8192  = 63488 bytes
#define FLASH_SMEM 63488

__global__ void __launch_bounds__(256) flash_hmma(const int* __restrict__ mask)
{
    extern __shared__ __align__(16) char smem[];
    __half (*sQ)[72] = (__half(*)[72])(smem);            // [128][72]
    __half (*sK)[72] = (__half(*)[72])(smem + 18432);    // [2*64][72]
    __half (*sV)[72] = (__half(*)[72])(smem + 36864);    // [2*64][72] natural [key][d]
    float* sMaskF    = (float*)(smem + 55296);           // [2048] whole row

    const int tid  = threadIdx.x;
    const int lane = tid & 31, warp = tid >> 5;
    const int gid  = lane >> 2, tig = lane & 3;
    const int g8   = lane >> 3, i8 = lane & 7;
    const int qt = blockIdx.x, h = blockIdx.y, b = blockIdx.z;
    const int qRow0 = b * SEQ + qt * 128;
    const int colBase = h * HDIM;
    const int wr0 = warp * 16;
    const float NEGM = -1.0e9f * LOG2E;
    const int NKC = SEQ / 64;   // 32 iterations

#define ISSUE(kc_, buf_) do {                                                 \
    const int kR_ = b * SEQ + (kc_) * 64;                                     \
    for (int j = 0; j < 2; j++) {                                             \
        int task = tid + j * 256, r = task >> 3, cc = (task & 7) * 8;         \
        CP16(sptr(&sK[(buf_) * 64 + r][cc]),                                  \
             g_kh + (size_t)(kR_ + r) * EDIM + colBase + cc);                 \
        CP16(sptr(&sV[(buf_) * 64 + r][cc]),                                  \
             g_vh + (size_t)(kR_ + r) * EDIM + colBase + cc);                 \
    }                                                                         \
    CP_COMMIT();                                                              \
} while (0)

    ISSUE(0, 0);

    // Q tile: 128 x 64 halfs = 1024 uint4 (synchronous)
    #pragma unroll
    for (int i = 0; i < 4; i++) {
        int idx = tid + i * 256;
        int r = idx >> 3, seg = idx & 7;
        *reinterpret_cast<uint4*>(&sQ[r][seg * 8]) =
            *reinterpret_cast<const uint4*>(
                g_qh + (size_t)(qRow0 + r) * EDIM + colBase + seg * 8);
    }
    // Whole mask row, converted once: 2048 ints -> 2048 floats (2 int4/thread)
    {
        const int4* mrow = (const int4*)(mask + b * SEQ);
        #pragma unroll
        for (int i = 0; i < 2; i++) {
            int idx = tid + i * 256;          // 0..511
            int4 m4 = mrow[idx];
            float4 f;
            f.x = m4.x ? NEGM : 0.f;
            f.y = m4.y ? NEGM : 0.f;
            f.z = m4.z ? NEGM : 0.f;
            f.w = m4.w ? NEGM : 0.f;
            reinterpret_cast<float4*>(sMaskF)[idx] = f;
        }
    }
    __syncthreads();

    uint32_t qf[4][4];
    #pragma unroll
    for (int t = 0; t < 4; t++)
        ldsm4(qf[t][0], qf[t][1], qf[t][2], qf[t][3],
              sptr(&sQ[wr0 + i8 + 8 * (g8 & 1)][t * 16 + 8 * (g8 >> 1)]));

    float of[8][4];
    #pragma unroll
    for (int nt = 0; nt < 8; nt++)
        #pragma unroll
        for (int i = 0; i < 4; i++) of[nt][i] = 0.f;
    float m_lo = -1e30f, m_hi = -1e30f, l_lo = 0.f, l_hi = 0.f;

    for (int kc = 0; kc < NKC; kc++) {
        const int buf = kc & 1;
        if (kc < NKC - 1) {
            ISSUE(kc + 1, buf ^ 1);
            asm volatile("cp.async.wait_group 1;" ::: "memory");
        } else {
            asm volatile("cp.async.wait_group 0;" ::: "memory");
        }
        __syncthreads();

        // S = Q K^T (fp32 frags), K B-fragments via ldsm4
        float sf[8][4];
        #pragma unroll
        for (int nt = 0; nt < 8; nt++)
            #pragma unroll
            for (int i = 0; i < 4; i++) sf[nt][i] = 0.f;
        #pragma unroll
        for (int t = 0; t < 4; t++)
            #pragma unroll
            for (int np = 0; np < 4; np++) {
                uint32_t k0r, k1r, k2r, k3r;
                ldsm4(k0r, k1r, k2r, k3r,
                      sptr(&sK[buf * 64 + np * 16 + i8 + 8 * (g8 >> 1)]
                              [t * 16 + 8 * (g8 & 1)]));
                mma16816(sf[2 * np],     qf[t], k0r, k1r);
                mma16816(sf[2 * np + 1], qf[t], k2r, k3r);
            }

        // scale into log2 domain + mask, then online softmax
        const float sc = 0.125f * LOG2E;
        const float* mrow = sMaskF + kc * 64;
        float mx_lo = -1e30f, mx_hi = -1e30f;
        #pragma unroll
        for (int nt = 0; nt < 8; nt++) {
            float p0 = mrow[nt * 8 + tig * 2];
            float p1 = mrow[nt * 8 + tig * 2 + 1];
            sf[nt][0] = fmaf(sf[nt][0], sc, p0);
            sf[nt][1] = fmaf(sf[nt][1], sc, p1);
            sf[nt][2] = fmaf(sf[nt][2], sc, p0);
            sf[nt][3] = fmaf(sf[nt][3], sc, p1);
            mx_lo = fmaxf(mx_lo, fmaxf(sf[nt][0], sf[nt][1]));
            mx_hi = fmaxf(mx_hi, fmaxf(sf[nt][2], sf[nt][3]));
        }
        mx_lo = fmaxf(mx_lo, __shfl_xor_sync(0xffffffffu, mx_lo, 1));
        mx_lo = fmaxf(mx_lo, __shfl_xor_sync(0xffffffffu, mx_lo, 2));
        mx_hi = fmaxf(mx_hi, __shfl_xor_sync(0xffffffffu, mx_hi, 1));
        mx_hi = fmaxf(mx_hi, __shfl_xor_sync(0xffffffffu, mx_hi, 2));
        float mn_lo = fmaxf(m_lo, mx_lo), mn_hi = fmaxf(m_hi, mx_hi);
        float al_lo = exp2f(m_lo - mn_lo), al_hi = exp2f(m_hi - mn_hi);

        float sum_lo = 0.f, sum_hi = 0.f;
        uint32_t pf[4][4];
        #pragma unroll
        for (int nt = 0; nt < 8; nt++) {
            float p0 = exp2f(sf[nt][0] - mn_lo);
            float p1 = exp2f(sf[nt][1] - mn_lo);
            float p2 = exp2f(sf[nt][2] - mn_hi);
            float p3 = exp2f(sf[nt][3] - mn_hi);
            sum_lo += p0 + p1; sum_hi += p2 + p3;
            int t = nt >> 1;
            __half2 lo2 = __floats2half2_rn(p0, p1);
            __half2 hi2 = __floats2half2_rn(p2, p3);
            if ((nt & 1) == 0) {
                pf[t][0] = *reinterpret_cast<uint32_t*>(&lo2);
                pf[t][1] = *reinterpret_cast<uint32_t*>(&hi2);
            } else {
                pf[t][2] = *reinterpret_cast<uint32_t*>(&lo2);
                pf[t][3] = *reinterpret_cast<uint32_t*>(&hi2);
            }
        }
        sum_lo += __shfl_xor_sync(0xffffffffu, sum_lo, 1);
        sum_lo += __shfl_xor_sync(0xffffffffu, sum_lo, 2);
        sum_hi += __shfl_xor_sync(0xffffffffu, sum_hi, 1);
        sum_hi += __shfl_xor_sync(0xffffffffu, sum_hi, 2);
        l_lo = l_lo * al_lo + sum_lo;  m_lo = mn_lo;
        l_hi = l_hi * al_hi + sum_hi;  m_hi = mn_hi;

        #pragma unroll
        for (int nt = 0; nt < 8; nt++) {
            of[nt][0] *= al_lo; of[nt][1] *= al_lo;
            of[nt][2] *= al_hi; of[nt][3] *= al_hi;
        }

        // O += P @ V   (V natural [key][d], B-fragments via ldsm4t)
        #pragma unroll
        for (int t = 0; t < 4; t++)
            #pragma unroll
            for (int np = 0; np < 4; np++) {
                uint32_t v0r, v1r, v2r, v3r;
                ldsm4t(v0r, v1r, v2r, v3r,
                       sptr(&sV[buf * 64 + t * 16 + i8 + 8 * (g8 & 1)]
                               [(2 * np + (g8 >> 1)) * 8]));
                mma16816(of[2 * np],     pf[t], v0r, v1r);
                mma16816(of[2 * np + 1], pf[t], v2r, v3r);
            }
        __syncthreads();
    }

    float r_lo = 1.f / l_lo, r_hi = 1.f / l_hi;
    #pragma unroll
    for (int nt = 0; nt < 8; nt++) {
        int col = colBase + nt * 8 + tig * 2;
        *reinterpret_cast<__half2*>(
            g_aoh + (size_t)(qRow0 + wr0 + gid) * EDIM + col) =
            __floats2half2_rn(of[nt][0] * r_lo, of[nt][1] * r_lo);
        *reinterpret_cast<__half2*>(
            g_aoh + (size_t)(qRow0 + wr0 + gid + 8) * EDIM + col) =
            __floats2half2_rn(of[nt][2] * r_hi, of[nt][3] * r_hi);
    }
#undef ISSUE
}

// ---------------------------------------------------------------------------
extern "C" void kernel_launch(void* const* d_in, const int* in_sizes, int n_in,
                              void* d_out, int out_size)
{
    (void)in_sizes; (void)n_in; (void)out_size;
    const float* value = (const float*)d_in[0];
    const float* key_  = (const float*)d_in[1];
    const float* query = (const float*)d_in[2];
    const int*   mask  = (const int*)d_in[3];
    const float* wq = (const float*)d_in[4];
    const float* bq = (const float*)d_in[5];
    const float* wk = (const float*)d_in[6];
    const float* bk = (const float*)d_in[7];
    const float* wv = (const float*)d_in[8];
    const float* bv = (const float*)d_in[9];
    const float* wo = (const float*)d_in[10];
    const float* bo = (const float*)d_in[11];
    float* out = (float*)d_out;

    __half *qh, *kh, *vh, *aoh, *wt;
    cudaGetSymbolAddress((void**)&qh,  g_qh);
    cudaGetSymbolAddress((void**)&kh,  g_kh);
    cudaGetSymbolAddress((void**)&vh,  g_vh);
    cudaGetSymbolAddress((void**)&aoh, g_aoh);
    cudaGetSymbolAddress((void**)&wt,  g_wt);
    __half* wt3 = wt + 3 * (size_t)EDIM * EDIM;

    cudaFuncSetAttribute(flash_hmma,
                         cudaFuncAttributeMaxDynamicSharedMemorySize, FLASH_SMEM);

    dim3 tGrid(16, 16), tBlk(32, 8);
    wt_convert_kernel<<<tGrid, tBlk>>>(wq, wt);
    wt_convert_kernel<<<tGrid, tBlk>>>(wk, wt + (size_t)EDIM * EDIM);
    wt_convert_kernel<<<tGrid, tBlk>>>(wv, wt + 2 * (size_t)EDIM * EDIM);
    wt_convert_kernel<<<tGrid, tBlk>>>(wo, wt3);

    // Q, K, V projections batched in one launch (fp32 in, fp16 out)
    hgemm_bias<true, true><<<dim3(EDIM / 128, NROWS / 128, 3), 256>>>(
        query, key_, value, wt, bq, bk, bv, qh, kh, vh);

    flash_hmma<<<dim3(SEQ / 128, HEADS, BATCH), 256, FLASH_SMEM>>>(mask);

    // Output projection (fp16 in, fp32 out)
    hgemm_bias<false, false><<<dim3(EDIM / 128, NROWS / 128, 1), 256>>>(
        aoh, aoh, aoh, wt3, bo, bo, bo, out, out, out);
}

// round 16
// speedup vs baseline: 1.3713x; 1.0454x over previous
#include <cuda_runtime.h>
#include <cuda_fp16.h>
#include <stdint.h>
#include <math.h>

#define NROWS (8 * 2048)
#define EDIM  512
#define HEADS 8
#define HDIM  64
#define SEQ   2048
#define BATCH 8
#define LOG2E 1.44269504f

// fp16 scratch (device globals: allocation-free per harness rules)
__device__ __align__(16) __half g_qh[NROWS * EDIM];
__device__ __align__(16) __half g_kh[NROWS * EDIM];
__device__ __align__(16) __half g_vh[NROWS * EDIM];
__device__ __align__(16) __half g_aoh[NROWS * EDIM];
__device__ __align__(16) __half g_wt[4 * EDIM * EDIM]; // 4 weights, [n][k] fp16

// ---------------------------------------------------------------------------
// PTX helpers
// ---------------------------------------------------------------------------
__device__ __forceinline__ uint32_t sptr(const void* p) {
    return (uint32_t)__cvta_generic_to_shared(p);
}

__device__ __forceinline__ void mma16816(float* c, const uint32_t* a,
                                         uint32_t b0, uint32_t b1)
{
    asm volatile(
        "mma.sync.aligned.m16n8k16.row.col.f32.f16.f16.f32 "
        "{%0,%1,%2,%3}, {%4,%5,%6,%7}, {%8,%9}, {%0,%1,%2,%3};"
        : "+f"(c[0]), "+f"(c[1]), "+f"(c[2]), "+f"(c[3])
        : "r"(a[0]), "r"(a[1]), "r"(a[2]), "r"(a[3]), "r"(b0), "r"(b1));
}

__device__ __forceinline__ void ldsm4(uint32_t& r0, uint32_t& r1,
                                      uint32_t& r2, uint32_t& r3, uint32_t a)
{
    asm volatile("ldmatrix.sync.aligned.m8n8.x4.shared.b16 {%0,%1,%2,%3}, [%4];"
                 : "=r"(r0), "=r"(r1), "=r"(r2), "=r"(r3) : "r"(a));
}

__device__ __forceinline__ void ldsm4t(uint32_t& r0, uint32_t& r1,
                                       uint32_t& r2, uint32_t& r3, uint32_t a)
{
    asm volatile("ldmatrix.sync.aligned.m8n8.x4.trans.shared.b16 {%0,%1,%2,%3}, [%4];"
                 : "=r"(r0), "=r"(r1), "=r"(r2), "=r"(r3) : "r"(a));
}

#define CP16(d, s) \
    asm volatile("cp.async.cg.shared.global [%0], [%1], 16;" :: "r"(d), "l"(s))
#define CP_COMMIT() asm volatile("cp.async.commit_group;" ::: "memory")

// ---------------------------------------------------------------------------
// Weight transpose+convert: Wt[n][k] = W[k][n], fp32 -> fp16.
// All four weights in ONE launch via blockIdx.z.
// ---------------------------------------------------------------------------
__global__ void wt_convert_kernel(const float* __restrict__ W0,
                                  const float* __restrict__ W1,
                                  const float* __restrict__ W2,
                                  const float* __restrict__ W3,
                                  __half* __restrict__ WtBase)
{
    const int z = blockIdx.z;
    const float* W = (z == 0) ? W0 : (z == 1) ? W1 : (z == 2) ? W2 : W3;
    __half* Wt = WtBase + (size_t)z * EDIM * EDIM;

    __shared__ float tile[32][33];
    int x = blockIdx.x * 32 + threadIdx.x;
    int y = blockIdx.y * 32 + threadIdx.y;
    #pragma unroll
    for (int i = 0; i < 32; i += 8)
        tile[threadIdx.y + i][threadIdx.x] = W[(size_t)(y + i) * EDIM + x];
    __syncthreads();
    int nk = blockIdx.y * 32 + threadIdx.x;
    int nn = blockIdx.x * 32 + threadIdx.y;
    #pragma unroll
    for (int i = 0; i < 32; i += 8)
        Wt[(size_t)(nn + i) * EDIM + nk] =
            __float2half(tile[threadIdx.x][threadIdx.y + i]);
}

// ---------------------------------------------------------------------------
// HGEMM (verbatim, hardware-verified): C = A @ Wt^T + bias.
// Block 128x128, k-step 32, 8 warps; QKV batched via blockIdx.z.
// ---------------------------------------------------------------------------
template <bool AF32, bool HALF_OUT>
__global__ void __launch_bounds__(256, 2) hgemm_bias(
    const void* __restrict__ A0, const void* __restrict__ A1,
    const void* __restrict__ A2, const __half* __restrict__ WtBase,
    const float* __restrict__ bias0, const float* __restrict__ bias1,
    const float* __restrict__ bias2,
    void* __restrict__ O0, void* __restrict__ O1, void* __restrict__ O2)
{
    __shared__ __align__(16) __half As[2][128][40];
    __shared__ __align__(16) __half Bs[2][128][40];

    const int z = blockIdx.z;
    const void*  A    = (z == 0) ? A0 : (z == 1) ? A1 : A2;
    const float* bias = (z == 0) ? bias0 : (z == 1) ? bias1 : bias2;
    void*        Cout = (z == 0) ? O0 : (z == 1) ? O1 : O2;
    const __half* Wt  = WtBase + (size_t)z * EDIM * EDIM;

    const int tid  = threadIdx.x;
    const int lane = tid & 31, warp = tid >> 5;
    const int gid  = lane >> 2, tig = lane & 3;
    const int g8   = lane >> 3, i8 = lane & 7;
    const int wm = warp >> 1, wn = warp & 1;
    const int rowBlock = blockIdx.y * 128, colBlock = blockIdx.x * 128;
    const int m0 = wm * 32, n0 = wn * 64;

    float c[2][8][4];
    #pragma unroll
    for (int mt = 0; mt < 2; mt++)
        #pragma unroll
        for (int nt = 0; nt < 8; nt++)
            #pragma unroll
            for (int i = 0; i < 4; i++) c[mt][nt][i] = 0.f;

    float4 aF[4];
    uint4  aH[2];
    uint4  bR[2];

#define LDG_TILE(kt) do {                                                     \
    int k0_ = (kt) * 32;                                                      \
    if (AF32) {                                                               \
        const float* Af_ = (const float*)A;                                   \
        for (int j = 0; j < 4; j++) {                                         \
            int task = tid + j * 256, r = task >> 3, cc = (task & 7) * 4;     \
            aF[j] = *(const float4*)(Af_ + (size_t)(rowBlock + r) * EDIM + k0_ + cc); \
        }                                                                     \
    } else {                                                                  \
        const __half* Ah_ = (const __half*)A;                                 \
        for (int j = 0; j < 2; j++) {                                         \
            int task = tid + j * 256, r = task >> 2, cc = (task & 3) * 8;     \
            aH[j] = *(const uint4*)(Ah_ + (size_t)(rowBlock + r) * EDIM + k0_ + cc); \
        }                                                                     \
    }                                                                         \
    for (int j = 0; j < 2; j++) {                                             \
        int task = tid + j * 256, r = task >> 2, cc = (task & 3) * 8;         \
        bR[j] = *(const uint4*)(Wt + (size_t)(colBlock + r) * EDIM + k0_ + cc); \
    }                                                                         \
} while (0)

#define STS_TILE(bf_) do {                                                    \
    if (AF32) {                                                               \
        for (int j = 0; j < 4; j++) {                                         \
            int task = tid + j * 256, r = task >> 3, cc = (task & 7) * 4;     \
            __half2 h0_ = __floats2half2_rn(aF[j].x, aF[j].y);                \
            __half2 h1_ = __floats2half2_rn(aF[j].z, aF[j].w);                \
            uint2 u_; u_.x = *(uint32_t*)&h0_; u_.y = *(uint32_t*)&h1_;       \
            *(uint2*)&As[bf_][r][cc] = u_;                                    \
        }                                                                     \
    } else {                                                                  \
        for (int j = 0; j < 2; j++) {                                         \
            int task = tid + j * 256, r = task >> 2, cc = (task & 3) * 8;     \
            *(uint4*)&As[bf_][r][cc] = aH[j];                                 \
        }                                                                     \
    }                                                                         \
    for (int j = 0; j < 2; j++) {                                             \
        int task = tid + j * 256, r = task >> 2, cc = (task & 3) * 8;         \
        *(uint4*)&Bs[bf_][r][cc] = bR[j];                                     \
    }                                                                         \
} while (0)

    LDG_TILE(0);
    STS_TILE(0);
    __syncthreads();

    for (int it = 0; it < 16; it++) {
        const int buf = it & 1;
        if (it < 15) LDG_TILE(it + 1);

        #pragma unroll
        for (int t = 0; t < 2; t++) {
            const int kk = t * 16;
            uint32_t af[2][4], bf[4][4];
            #pragma unroll
            for (int mt = 0; mt < 2; mt++)
                ldsm4(af[mt][0], af[mt][1], af[mt][2], af[mt][3],
                      sptr(&As[buf][m0 + mt * 16 + i8 + 8 * (g8 & 1)]
                              [kk + 8 * (g8 >> 1)]));
            #pragma unroll
            for (int np = 0; np < 4; np++)
                ldsm4(bf[np][0], bf[np][1], bf[np][2], bf[np][3],
                      sptr(&Bs[buf][n0 + np * 16 + i8 + 8 * (g8 >> 1)]
                              [kk + 8 * (g8 & 1)]));
            #pragma unroll
            for (int mt = 0; mt < 2; mt++)
                #pragma unroll
                for (int np = 0; np < 4; np++) {
                    mma16816(c[mt][2 * np],     af[mt], bf[np][0], bf[np][1]);
                    mma16816(c[mt][2 * np + 1], af[mt], bf[np][2], bf[np][3]);
                }
        }

        if (it < 15) STS_TILE(buf ^ 1);
        __syncthreads();
    }

    #pragma unroll
    for (int mt = 0; mt < 2; mt++) {
        int r0 = rowBlock + m0 + mt * 16 + gid;
        #pragma unroll
        for (int nt = 0; nt < 8; nt++) {
            int col = colBlock + n0 + nt * 8 + tig * 2;
            float b0v = bias[col], b1v = bias[col + 1];
            if (HALF_OUT) {
                __half* o = (__half*)Cout;
                *reinterpret_cast<__half2*>(o + (size_t)r0 * EDIM + col) =
                    __floats2half2_rn(c[mt][nt][0] + b0v, c[mt][nt][1] + b1v);
                *reinterpret_cast<__half2*>(o + (size_t)(r0 + 8) * EDIM + col) =
                    __floats2half2_rn(c[mt][nt][2] + b0v, c[mt][nt][3] + b1v);
            } else {
                float* o = (float*)Cout;
                *reinterpret_cast<float2*>(o + (size_t)r0 * EDIM + col) =
                    make_float2(c[mt][nt][0] + b0v, c[mt][nt][1] + b1v);
                *reinterpret_cast<float2*>(o + (size_t)(r0 + 8) * EDIM + col) =
                    make_float2(c[mt][nt][2] + b0v, c[mt][nt][3] + b1v);
            }
        }
    }
#undef LDG_TILE
#undef STS_TILE
}

// ---------------------------------------------------------------------------
// Flash attention, HMMA. Br=128, Bc=64, 8 warps; warp w owns rows w*16..+15.
// cp.async double-buffered K/V; mask hoisted to per-CTA preamble.
// THIS ROUND: __launch_bounds__(256, 2) to cap regs at 128 and run
// 2 CTAs/SM (smem 2x63488 = 127KB fits) -> cross-CTA phase overlap.
// ---------------------------------------------------------------------------
// smem: sQ 18432 | sK 2x9216 | sV 2x9216 | maskrow 8192  = 63488 bytes
#define FLASH_SMEM 63488

__global__ void __launch_bounds__(256, 2) flash_hmma(const int* __restrict__ mask)
{
    extern __shared__ __align__(16) char smem[];
    __half (*sQ)[72] = (__half(*)[72])(smem);            // [128][72]
    __half (*sK)[72] = (__half(*)[72])(smem + 18432);    // [2*64][72]
    __half (*sV)[72] = (__half(*)[72])(smem + 36864);    // [2*64][72] natural [key][d]
    float* sMaskF    = (float*)(smem + 55296);           // [2048] whole row

    const int tid  = threadIdx.x;
    const int lane = tid & 31, warp = tid >> 5;
    const int gid  = lane >> 2, tig = lane & 3;
    const int g8   = lane >> 3, i8 = lane & 7;
    const int qt = blockIdx.x, h = blockIdx.y, b = blockIdx.z;
    const int qRow0 = b * SEQ + qt * 128;
    const int colBase = h * HDIM;
    const int wr0 = warp * 16;
    const float NEGM = -1.0e9f * LOG2E;
    const int NKC = SEQ / 64;   // 32 iterations

#define ISSUE(kc_, buf_) do {                                                 \
    const int kR_ = b * SEQ + (kc_) * 64;                                     \
    for (int j = 0; j < 2; j++) {                                             \
        int task = tid + j * 256, r = task >> 3, cc = (task & 7) * 8;         \
        CP16(sptr(&sK[(buf_) * 64 + r][cc]),                                  \
             g_kh + (size_t)(kR_ + r) * EDIM + colBase + cc);                 \
        CP16(sptr(&sV[(buf_) * 64 + r][cc]),                                  \
             g_vh + (size_t)(kR_ + r) * EDIM + colBase + cc);                 \
    }                                                                         \
    CP_COMMIT();                                                              \
} while (0)

    ISSUE(0, 0);

    // Q tile: 128 x 64 halfs = 1024 uint4 (synchronous)
    #pragma unroll
    for (int i = 0; i < 4; i++) {
        int idx = tid + i * 256;
        int r = idx >> 3, seg = idx & 7;
        *reinterpret_cast<uint4*>(&sQ[r][seg * 8]) =
            *reinterpret_cast<const uint4*>(
                g_qh + (size_t)(qRow0 + r) * EDIM + colBase + seg * 8);
    }
    // Whole mask row, converted once: 2048 ints -> 2048 floats (2 int4/thread)
    {
        const int4* mrow = (const int4*)(mask + b * SEQ);
        #pragma unroll
        for (int i = 0; i < 2; i++) {
            int idx = tid + i * 256;          // 0..511
            int4 m4 = mrow[idx];
            float4 f;
            f.x = m4.x ? NEGM : 0.f;
            f.y = m4.y ? NEGM : 0.f;
            f.z = m4.z ? NEGM : 0.f;
            f.w = m4.w ? NEGM : 0.f;
            reinterpret_cast<float4*>(sMaskF)[idx] = f;
        }
    }
    __syncthreads();

    uint32_t qf[4][4];
    #pragma unroll
    for (int t = 0; t < 4; t++)
        ldsm4(qf[t][0], qf[t][1], qf[t][2], qf[t][3],
              sptr(&sQ[wr0 + i8 + 8 * (g8 & 1)][t * 16 + 8 * (g8 >> 1)]));

    float of[8][4];
    #pragma unroll
    for (int nt = 0; nt < 8; nt++)
        #pragma unroll
        for (int i = 0; i < 4; i++) of[nt][i] = 0.f;
    float m_lo = -1e30f, m_hi = -1e30f, l_lo = 0.f, l_hi = 0.f;

    for (int kc = 0; kc < NKC; kc++) {
        const int buf = kc & 1;
        if (kc < NKC - 1) {
            ISSUE(kc + 1, buf ^ 1);
            asm volatile("cp.async.wait_group 1;" ::: "memory");
        } else {
            asm volatile("cp.async.wait_group 0;" ::: "memory");
        }
        __syncthreads();

        // S = Q K^T (fp32 frags), K B-fragments via ldsm4
        float sf[8][4];
        #pragma unroll
        for (int nt = 0; nt < 8; nt++)
            #pragma unroll
            for (int i = 0; i < 4; i++) sf[nt][i] = 0.f;
        #pragma unroll
        for (int t = 0; t < 4; t++)
            #pragma unroll
            for (int np = 0; np < 4; np++) {
                uint32_t k0r, k1r, k2r, k3r;
                ldsm4(k0r, k1r, k2r, k3r,
                      sptr(&sK[buf * 64 + np * 16 + i8 + 8 * (g8 >> 1)]
                              [t * 16 + 8 * (g8 & 1)]));
                mma16816(sf[2 * np],     qf[t], k0r, k1r);
                mma16816(sf[2 * np + 1], qf[t], k2r, k3r);
            }

        // scale into log2 domain + mask, then online softmax
        const float sc = 0.125f * LOG2E;
        const float* mrow = sMaskF + kc * 64;
        float mx_lo = -1e30f, mx_hi = -1e30f;
        #pragma unroll
        for (int nt = 0; nt < 8; nt++) {
            float p0 = mrow[nt * 8 + tig * 2];
            float p1 = mrow[nt * 8 + tig * 2 + 1];
            sf[nt][0] = fmaf(sf[nt][0], sc, p0);
            sf[nt][1] = fmaf(sf[nt][1], sc, p1);
            sf[nt][2] = fmaf(sf[nt][2], sc, p0);
            sf[nt][3] = fmaf(sf[nt][3], sc, p1);
            mx_lo = fmaxf(mx_lo, fmaxf(sf[nt][0], sf[nt][1]));
            mx_hi = fmaxf(mx_hi, fmaxf(sf[nt][2], sf[nt][3]));
        }
        mx_lo = fmaxf(mx_lo, __shfl_xor_sync(0xffffffffu, mx_lo, 1));
        mx_lo = fmaxf(mx_lo, __shfl_xor_sync(0xffffffffu, mx_lo, 2));
        mx_hi = fmaxf(mx_hi, __shfl_xor_sync(0xffffffffu, mx_hi, 1));
        mx_hi = fmaxf(mx_hi, __shfl_xor_sync(0xffffffffu, mx_hi, 2));
        float mn_lo = fmaxf(m_lo, mx_lo), mn_hi = fmaxf(m_hi, mx_hi);
        float al_lo = exp2f(m_lo - mn_lo), al_hi = exp2f(m_hi - mn_hi);

        float sum_lo = 0.f, sum_hi = 0.f;
        uint32_t pf[4][4];
        #pragma unroll
        for (int nt = 0; nt < 8; nt++) {
            float p0 = exp2f(sf[nt][0] - mn_lo);
            float p1 = exp2f(sf[nt][1] - mn_lo);
            float p2 = exp2f(sf[nt][2] - mn_hi);
            float p3 = exp2f(sf[nt][3] - mn_hi);
            sum_lo += p0 + p1; sum_hi += p2 + p3;
            int t = nt >> 1;
            __half2 lo2 = __floats2half2_rn(p0, p1);
            __half2 hi2 = __floats2half2_rn(p2, p3);
            if ((nt & 1) == 0) {
                pf[t][0] = *reinterpret_cast<uint32_t*>(&lo2);
                pf[t][1] = *reinterpret_cast<uint32_t*>(&hi2);
            } else {
                pf[t][2] = *reinterpret_cast<uint32_t*>(&lo2);
                pf[t][3] = *reinterpret_cast<uint32_t*>(&hi2);
            }
        }
        sum_lo += __shfl_xor_sync(0xffffffffu, sum_lo, 1);
        sum_lo += __shfl_xor_sync(0xffffffffu, sum_lo, 2);
        sum_hi += __shfl_xor_sync(0xffffffffu, sum_hi, 1);
        sum_hi += __shfl_xor_sync(0xffffffffu, sum_hi, 2);
        l_lo = l_lo * al_lo + sum_lo;  m_lo = mn_lo;
        l_hi = l_hi * al_hi + sum_hi;  m_hi = mn_hi;

        #pragma unroll
        for (int nt = 0; nt < 8; nt++) {
            of[nt][0] *= al_lo; of[nt][1] *= al_lo;
            of[nt][2] *= al_hi; of[nt][3] *= al_hi;
        }

        // O += P @ V   (V natural [key][d], B-fragments via ldsm4t)
        #pragma unroll
        for (int t = 0; t < 4; t++)
            #pragma unroll
            for (int np = 0; np < 4; np++) {
                uint32_t v0r, v1r, v2r, v3r;
                ldsm4t(v0r, v1r, v2r, v3r,
                       sptr(&sV[buf * 64 + t * 16 + i8 + 8 * (g8 & 1)]
                               [(2 * np + (g8 >> 1)) * 8]));
                mma16816(of[2 * np],     pf[t], v0r, v1r);
                mma16816(of[2 * np + 1], pf[t], v2r, v3r);
            }
        __syncthreads();
    }

    float r_lo = 1.f / l_lo, r_hi = 1.f / l_hi;
    #pragma unroll
    for (int nt = 0; nt < 8; nt++) {
        int col = colBase + nt * 8 + tig * 2;
        *reinterpret_cast<__half2*>(
            g_aoh + (size_t)(qRow0 + wr0 + gid) * EDIM + col) =
            __floats2half2_rn(of[nt][0] * r_lo, of[nt][1] * r_lo);
        *reinterpret_cast<__half2*>(
            g_aoh + (size_t)(qRow0 + wr0 + gid + 8) * EDIM + col) =
            __floats2half2_rn(of[nt][2] * r_hi, of[nt][3] * r_hi);
    }
#undef ISSUE
}

// ---------------------------------------------------------------------------
extern "C" void kernel_launch(void* const* d_in, const int* in_sizes, int n_in,
                              void* d_out, int out_size)
{
    (void)in_sizes; (void)n_in; (void)out_size;
    const float* value = (const float*)d_in[0];
    const float* key_  = (const float*)d_in[1];
    const float* query = (const float*)d_in[2];
    const int*   mask  = (const int*)d_in[3];
    const float* wq = (const float*)d_in[4];
    const float* bq = (const float*)d_in[5];
    const float* wk = (const float*)d_in[6];
    const float* bk = (const float*)d_in[7];
    const float* wv = (const float*)d_in[8];
    const float* bv = (const float*)d_in[9];
    const float* wo = (const float*)d_in[10];
    const float* bo = (const float*)d_in[11];
    float* out = (float*)d_out;

    __half *qh, *kh, *vh, *aoh, *wt;
    cudaGetSymbolAddress((void**)&qh,  g_qh);
    cudaGetSymbolAddress((void**)&kh,  g_kh);
    cudaGetSymbolAddress((void**)&vh,  g_vh);
    cudaGetSymbolAddress((void**)&aoh, g_aoh);
    cudaGetSymbolAddress((void**)&wt,  g_wt);
    __half* wt3 = wt + 3 * (size_t)EDIM * EDIM;

    cudaFuncSetAttribute(flash_hmma,
                         cudaFuncAttributeMaxDynamicSharedMemorySize, FLASH_SMEM);

    // All four weight converts in one launch
    wt_convert_kernel<<<dim3(16, 16, 4), dim3(32, 8)>>>(wq, wk, wv, wo, wt);

    // Q, K, V projections batched in one launch (fp32 in, fp16 out)
    hgemm_bias<true, true><<<dim3(EDIM / 128, NROWS / 128, 3), 256>>>(
        query, key_, value, wt, bq, bk, bv, qh, kh, vh);

    flash_hmma<<<dim3(SEQ / 128, HEADS, BATCH), 256, FLASH_SMEM>>>(mask);

    // Output projection (fp16 in, fp32 out)
    hgemm_bias<false, false><<<dim3(EDIM / 128, NROWS / 128, 1), 256>>>(
        aoh, aoh, aoh, wt3, bo, bo, bo, out, out, out);
}